// round 15
// baseline (speedup 1.0000x reference)
#include <cuda_runtime.h>
#include <cuda_bf16.h>
#include <mma.h>
#include <cstdint>

using namespace nvcuda;

// Problem constants
constexpr int kN  = 50000;
constexpr int kE  = 800000;
constexpr int kG  = 128;
constexpr int kD  = 128;
constexpr int kH  = 512;
constexpr int kH2 = 1024;
constexpr int kL  = 4;
#define BNS 0.9999950000374997f   // 1/sqrt(1+1e-5)

// ---------------- scratch (no cudaMalloc allowed) ----------------
__device__ float g_h   [(size_t)kN * kH];
__device__ float g_vf  [kG * kH];
__device__ int   g_goff[kG + 1];

// CSR structures
__device__ int g_deg   [kN];
__device__ int g_cur   [kN];
__device__ int g_rowptr[kN + 1];
__device__ int g_esrc  [kE];

// bf16 split buffers
__device__ __nv_bfloat16 g_ahi[(size_t)kN * kH];
__device__ __nv_bfloat16 g_alo[(size_t)kN * kH];
__device__ __nv_bfloat16 g_bhi[(size_t)kN * kH2];
__device__ __nv_bfloat16 g_blo[(size_t)kN * kH2];
__device__ __nv_bfloat16 g_phi[kG * kH];
__device__ __nv_bfloat16 g_plo[kG * kH];
__device__ __nv_bfloat16 g_qhi[kG * kH2];
__device__ __nv_bfloat16 g_qlo[kG * kH2];

// Split weights, layout [K, Nc] row-major, bf16 hi/lo
constexpr size_t OFF_c1W1 = 0;                            // [128,1024]
constexpr size_t OFF_c1W2 = OFF_c1W1 + 128 * 1024;        // [1024,512]
constexpr size_t OFF_csW1 = OFF_c1W2 + 1024 * 512;        // 4 x [512,1024]
constexpr size_t OFF_csW2 = OFF_csW1 + 4ull * 512 * 1024; // 4 x [1024,512]
constexpr size_t OFF_vW1  = OFF_csW2 + 4ull * 1024 * 512; // [512,1024]
constexpr size_t OFF_vW2  = OFF_vW1 + 512 * 1024;         // [1024,512]
constexpr size_t WT_TOTAL = OFF_vW2 + 1024 * 512;
__device__ __nv_bfloat16 g_wthi[WT_TOTAL];
__device__ __nv_bfloat16 g_wtlo[WT_TOTAL];

// ---------------- helpers ----------------
__device__ __forceinline__ uint32_t smem_u32(const void* p) {
    uint32_t a;
    asm("{ .reg .u64 t; cvta.to.shared.u64 t, %1; cvt.u32.u64 %0, t; }" : "=r"(a) : "l"(p));
    return a;
}
__device__ __forceinline__ void cp16(uint32_t saddr, const void* gaddr) {
    asm volatile("cp.async.cg.shared.global [%0], [%1], 16;" :: "r"(saddr), "l"(gaddr) : "memory");
}
#define CP_COMMIT() asm volatile("cp.async.commit_group;" ::: "memory")
#define CP_WAIT(n)  asm volatile("cp.async.wait_group %0;" :: "n"(n) : "memory")

// pack 4 floats -> bf16 hi/lo pairs
__device__ __forceinline__ void split4(float4 v, uint2& uh, uint2& ul) {
    unsigned short hx = __bfloat16_as_ushort(__float2bfloat16(v.x));
    unsigned short hy = __bfloat16_as_ushort(__float2bfloat16(v.y));
    unsigned short hz = __bfloat16_as_ushort(__float2bfloat16(v.z));
    unsigned short hw = __bfloat16_as_ushort(__float2bfloat16(v.w));
    float fx = __bfloat162float(__ushort_as_bfloat16(hx));
    float fy = __bfloat162float(__ushort_as_bfloat16(hy));
    float fz = __bfloat162float(__ushort_as_bfloat16(hz));
    float fw = __bfloat162float(__ushort_as_bfloat16(hw));
    unsigned short lx = __bfloat16_as_ushort(__float2bfloat16(v.x - fx));
    unsigned short ly = __bfloat16_as_ushort(__float2bfloat16(v.y - fy));
    unsigned short lz = __bfloat16_as_ushort(__float2bfloat16(v.z - fz));
    unsigned short lw = __bfloat16_as_ushort(__float2bfloat16(v.w - fw));
    uh.x = (uint32_t)hx | ((uint32_t)hy << 16);
    uh.y = (uint32_t)hz | ((uint32_t)hw << 16);
    ul.x = (uint32_t)lx | ((uint32_t)ly << 16);
    ul.y = (uint32_t)lz | ((uint32_t)lw << 16);
}

// ---------------- GEMM smem layout (tile 128x128, BK=32, 2 stages) ----------------
constexpr int A_LD   = 40;                  // 32 + 8 pad
constexpr int B_LD   = 136;                 // 128 + 8 pad
constexpr int A_MATB = 128 * A_LD * 2;      // 10240
constexpr int B_MATB = 32 * B_LD * 2;       // 8704
constexpr int ST_AH  = 0;
constexpr int ST_AL  = A_MATB;
constexpr int ST_BH  = 2 * A_MATB;
constexpr int ST_BL  = 2 * A_MATB + B_MATB;
constexpr int STAGE  = 2 * A_MATB + 2 * B_MATB; // 37888
constexpr int NSTG   = 2;
constexpr int OFF_SC = NSTG * STAGE;        // 75776
constexpr int OFF_SH = OFF_SC + 512;
constexpr int DSMEM  = OFF_SH + 512;        // 76800  (x2 CTAs = 150KB <= 228KB)

// ---------------- bf16-split GEMM: out = act((A@W + lb)*(ga*BNS) + be) ----------------
// CTA 128x128, 8 warps (4x2), warp tile 32x64, wmma 16x16x16, 3-term split,
// 2-stage cp.async, 2 CTAs/SM.   (R12-proven numerics, unchanged)
template<int RELU, int SPLIT>
__global__ void __launch_bounds__(256, 2) gemm_bf16(
    const __nv_bfloat16* __restrict__ Ahi, const __nv_bfloat16* __restrict__ Alo,
    const __nv_bfloat16* __restrict__ Bhi, const __nv_bfloat16* __restrict__ Blo,
    const float* __restrict__ lb, const float* __restrict__ ga,
    const float* __restrict__ be, float* __restrict__ C,
    __nv_bfloat16* __restrict__ Chi, __nv_bfloat16* __restrict__ Clo,
    int M, int K, int Nc)
{
    extern __shared__ char sm[];
    const uint32_t sbase = smem_u32(sm);

    const int tid  = threadIdx.x;
    const int warp = tid >> 5, lane = tid & 31;
    const int wm   = warp >> 1, wn = warp & 1;
    const int bm0  = blockIdx.y * 128, bn0 = blockIdx.x * 128;

    if (tid < 128) {
        float s = ga[bn0 + tid] * BNS;
        ((float*)(sm + OFF_SC))[tid] = s;
        ((float*)(sm + OFF_SH))[tid] = fmaf(lb[bn0 + tid], s, be[bn0 + tid]);
    }

    wmma::fragment<wmma::accumulator, 16, 16, 16, float> acc[2][4];
#pragma unroll
    for (int i = 0; i < 2; i++)
#pragma unroll
        for (int j = 0; j < 4; j++) wmma::fill_fragment(acc[i][j], 0.0f);

    const int nK = K >> 5;

    auto issue = [&](int c) {
        const int buf = c & 1;
        const int k0  = c << 5;
        const uint32_t sb = sbase + buf * STAGE;
#pragma unroll
        for (int t = 0; t < 2; t++) {
            int chunk = tid + (t << 8);
            int row   = chunk >> 2;
            int col8  = (chunk & 3) << 3;
            int gr    = bm0 + row;
            if (gr < M) {
                uint32_t off = (uint32_t)(row * A_LD + col8) * 2;
                size_t g = (size_t)gr * K + k0 + col8;
                cp16(sb + ST_AH + off, Ahi + g);
                cp16(sb + ST_AL + off, Alo + g);
            }
        }
#pragma unroll
        for (int t = 0; t < 2; t++) {
            int chunk = tid + (t << 8);
            int row   = chunk >> 4;
            int col8  = (chunk & 15) << 3;
            uint32_t off = (uint32_t)(row * B_LD + col8) * 2;
            size_t g = (size_t)(k0 + row) * Nc + bn0 + col8;
            cp16(sb + ST_BH + off, Bhi + g);
            cp16(sb + ST_BL + off, Blo + g);
        }
        CP_COMMIT();
    };

    issue(0);
    for (int c = 0; c < nK; c++) {
        if (c + 1 < nK) { issue(c + 1); CP_WAIT(1); }
        else            { CP_WAIT(0); }
        __syncthreads();

        const char* st = sm + (c & 1) * STAGE;
        const __nv_bfloat16* sAh = (const __nv_bfloat16*)(st + ST_AH);
        const __nv_bfloat16* sAl = (const __nv_bfloat16*)(st + ST_AL);
        const __nv_bfloat16* sBh = (const __nv_bfloat16*)(st + ST_BH);
        const __nv_bfloat16* sBl = (const __nv_bfloat16*)(st + ST_BL);
#pragma unroll
        for (int ks = 0; ks < 2; ks++) {
            const int kk = ks << 4;
            wmma::fragment<wmma::matrix_a, 16, 16, 16, __nv_bfloat16, wmma::row_major> ah[2], al[2];
#pragma unroll
            for (int i = 0; i < 2; i++) {
                wmma::load_matrix_sync(ah[i], sAh + (wm * 32 + i * 16) * A_LD + kk, A_LD);
                wmma::load_matrix_sync(al[i], sAl + (wm * 32 + i * 16) * A_LD + kk, A_LD);
            }
#pragma unroll
            for (int j = 0; j < 4; j++) {
                wmma::fragment<wmma::matrix_b, 16, 16, 16, __nv_bfloat16, wmma::row_major> bh, bl;
                wmma::load_matrix_sync(bh, sBh + kk * B_LD + wn * 64 + j * 16, B_LD);
                wmma::load_matrix_sync(bl, sBl + kk * B_LD + wn * 64 + j * 16, B_LD);
#pragma unroll
                for (int i = 0; i < 2; i++) {
                    wmma::mma_sync(acc[i][j], ah[i], bh, acc[i][j]);
                    wmma::mma_sync(acc[i][j], ah[i], bl, acc[i][j]);
                    wmma::mma_sync(acc[i][j], al[i], bh, acc[i][j]);
                }
            }
        }
        __syncthreads();
    }

    // epilogue: stage 16x16 tiles via smem, fused BN/bias/ReLU (+optional split)
    float* stage = (float*)(sm + warp * 1280);
    const float* sc = (const float*)(sm + OFF_SC);
    const float* sh = (const float*)(sm + OFF_SH);
#pragma unroll
    for (int i = 0; i < 2; i++)
#pragma unroll
        for (int j = 0; j < 4; j++) {
            __syncwarp();
            wmma::store_matrix_sync(stage, acc[i][j], 20, wmma::mem_row_major);
            __syncwarp();
#pragma unroll
            for (int t = lane; t < 256; t += 32) {
                int r   = t >> 4, cc = t & 15;
                int gr  = bm0 + wm * 32 + i * 16 + r;
                int gcl = wn * 64 + j * 16 + cc;
                if (gr < M) {
                    float o = fmaf(stage[r * 20 + cc], sc[gcl], sh[gcl]);
                    if (RELU) o = fmaxf(o, 0.0f);
                    size_t idx = (size_t)gr * Nc + bn0 + gcl;
                    if (SPLIT) {
                        __nv_bfloat16 hi = __float2bfloat16(o);
                        Chi[idx] = hi;
                        Clo[idx] = __float2bfloat16(o - __bfloat162float(hi));
                    } else {
                        C[idx] = o;
                    }
                }
            }
        }
}

// ---------------- prep: zero deg/cur + split c1_W1 to bf16 hi/lo ----------------
// blocks [0,128): split c1_W1 (131072 floats = 32768 float4)
// blocks [128,...): zero deg and cur
__global__ void prep_k(const float* __restrict__ W,
                       __nv_bfloat16* __restrict__ hi, __nv_bfloat16* __restrict__ lo,
                       int* __restrict__ deg, int* __restrict__ cur) {
    int b = blockIdx.x;
    if (b < 128) {
        int i = b * 256 + threadIdx.x;
        uint2 uh, ul;
        split4(reinterpret_cast<const float4*>(W)[i], uh, ul);
        reinterpret_cast<uint2*>(hi)[i] = uh;
        reinterpret_cast<uint2*>(lo)[i] = ul;
    } else {
        int i = (b - 128) * 256 + threadIdx.x;
        if (i < kN) { deg[i] = 0; cur[i] = 0; }
    }
}

// ---------------- fp32 -> bf16 hi/lo split (weights) ----------------
__global__ void split_k(const float* __restrict__ A, __nv_bfloat16* __restrict__ hi,
                        __nv_bfloat16* __restrict__ lo, int n4) {
    int i = blockIdx.x * blockDim.x + threadIdx.x;
    if (i >= n4) return;
    uint2 uh, ul;
    split4(reinterpret_cast<const float4*>(A)[i], uh, ul);
    reinterpret_cast<uint2*>(hi)[i] = uh;
    reinterpret_cast<uint2*>(lo)[i] = ul;
}

// ---------------- CSR build ----------------
__global__ void degcount_k(const int* __restrict__ dst, int* __restrict__ deg) {
    int e = blockIdx.x * blockDim.x + threadIdx.x;
    if (e < kE) atomicAdd(&deg[__ldg(dst + e)], 1);
}

__global__ void scan_k(const int* __restrict__ deg, int* __restrict__ rowptr) {
    __shared__ int part[1024];
    __shared__ int total;
    const int t  = threadIdx.x;
    const int CH = (kN + 1023) / 1024;
    int start = t * CH;
    int end   = start + CH; if (end > kN) end = kN;
    int s = 0;
    for (int i = start; i < end; i++) s += deg[i];
    part[t] = s;
    __syncthreads();
    if (t == 0) {
        int run = 0;
        for (int j = 0; j < 1024; j++) { int v = part[j]; part[j] = run; run += v; }
        total = run;
    }
    __syncthreads();
    int run = part[t];
    for (int i = start; i < end; i++) { rowptr[i] = run; run += deg[i]; }
    if (t == 0) rowptr[kN] = total;
}

__global__ void fill_k(const int* __restrict__ src, const int* __restrict__ dst,
                       const int* __restrict__ rowptr, int* __restrict__ cur,
                       int* __restrict__ esrc) {
    int e = blockIdx.x * blockDim.x + threadIdx.x;
    if (e >= kE) return;
    int d = __ldg(dst + e);
    int pos = rowptr[d] + atomicAdd(&cur[d], 1);
    esrc[pos] = __ldg(src + e);
}

// ---------------- graph offsets: histogram + scan of sorted batch, one block ----------------
__global__ void countgscan_k(const int* __restrict__ batch, int* __restrict__ goff) {
    __shared__ int scnt[kG];
    const int t = threadIdx.x;
    for (int g = t; g < kG; g += blockDim.x) scnt[g] = 0;
    __syncthreads();
    for (int n = t; n < kN; n += blockDim.x) atomicAdd(&scnt[__ldg(batch + n)], 1);
    __syncthreads();
    if (t == 0) {
        int run = 0;
        for (int g = 0; g < kG; g++) { goff[g] = run; run += scnt[g]; }
        goff[kG] = run;
    }
}

// ---------------- CSR gather aggregation (+virtual add) + fused bf16 hi/lo split ----------------
// out[n] = f(n) + sum_{s in N(n)} f(s), f(n) = feat[n] (+ vf[batch[n]] if VIRT)
template<int F, int VIRT>
__global__ void __launch_bounds__(256) aggregate_k(
    const float* __restrict__ feat, const float* __restrict__ vf,
    const int* __restrict__ batch,
    const int* __restrict__ rowptr, const int* __restrict__ esrc,
    __nv_bfloat16* __restrict__ hi, __nv_bfloat16* __restrict__ lo)
{
    constexpr int C4  = F / 4;
    constexpr int NPB = 256 / C4;
    const int n = blockIdx.x * NPB + (threadIdx.x / C4);
    const int c = threadIdx.x & (C4 - 1);
    const float4* f4  = reinterpret_cast<const float4*>(feat);
    const float4* vf4 = reinterpret_cast<const float4*>(vf);
    float4 acc = f4[(size_t)n * C4 + c];
    if (VIRT) {
        float4 v = vf4[(size_t)__ldg(batch + n) * C4 + c];
        acc.x += v.x; acc.y += v.y; acc.z += v.z; acc.w += v.w;
    }
    const int p0 = __ldg(rowptr + n), p1 = __ldg(rowptr + n + 1);
    int p = p0;
    for (; p + 4 <= p1; p += 4) {
        int s0 = __ldg(esrc + p),     s1 = __ldg(esrc + p + 1);
        int s2 = __ldg(esrc + p + 2), s3 = __ldg(esrc + p + 3);
        float4 v0 = f4[(size_t)s0 * C4 + c];
        float4 v1 = f4[(size_t)s1 * C4 + c];
        float4 v2 = f4[(size_t)s2 * C4 + c];
        float4 v3 = f4[(size_t)s3 * C4 + c];
        if (VIRT) {
            float4 w0 = vf4[(size_t)__ldg(batch + s0) * C4 + c];
            float4 w1 = vf4[(size_t)__ldg(batch + s1) * C4 + c];
            float4 w2 = vf4[(size_t)__ldg(batch + s2) * C4 + c];
            float4 w3 = vf4[(size_t)__ldg(batch + s3) * C4 + c];
            v0.x += w0.x; v0.y += w0.y; v0.z += w0.z; v0.w += w0.w;
            v1.x += w1.x; v1.y += w1.y; v1.z += w1.z; v1.w += w1.w;
            v2.x += w2.x; v2.y += w2.y; v2.z += w2.z; v2.w += w2.w;
            v3.x += w3.x; v3.y += w3.y; v3.z += w3.z; v3.w += w3.w;
        }
        acc.x += (v0.x + v1.x) + (v2.x + v3.x);
        acc.y += (v0.y + v1.y) + (v2.y + v3.y);
        acc.z += (v0.z + v1.z) + (v2.z + v3.z);
        acc.w += (v0.w + v1.w) + (v2.w + v3.w);
    }
    for (; p < p1; p++) {
        int s = __ldg(esrc + p);
        float4 v = f4[(size_t)s * C4 + c];
        if (VIRT) {
            float4 w = vf4[(size_t)__ldg(batch + s) * C4 + c];
            v.x += w.x; v.y += w.y; v.z += w.z; v.w += w.w;
        }
        acc.x += v.x; acc.y += v.y; acc.z += v.z; acc.w += v.w;
    }
    uint2 uh, ul;
    split4(acc, uh, ul);
    reinterpret_cast<uint2*>(hi)[(size_t)n * C4 + c] = uh;
    reinterpret_cast<uint2*>(lo)[(size_t)n * C4 + c] = ul;
}

// ---------------- segmented pools over sorted batch ----------------
__global__ void pool_virt_k(const float* __restrict__ h, const int* __restrict__ goff,
                            const float* __restrict__ vf,
                            __nv_bfloat16* __restrict__ phi, __nv_bfloat16* __restrict__ plo) {
    const int g = blockIdx.x, c = threadIdx.x;
    const float4* h4 = reinterpret_cast<const float4*>(h);
    float4 a0 = reinterpret_cast<const float4*>(vf)[(size_t)g * 128 + c];
    float4 a1 = make_float4(0.f, 0.f, 0.f, 0.f);
    const int n0 = __ldg(goff + g), n1 = __ldg(goff + g + 1);
    int n = n0;
    for (; n + 2 <= n1; n += 2) {
        float4 v0 = h4[(size_t)n * 128 + c];
        float4 v1 = h4[(size_t)(n + 1) * 128 + c];
        a0.x += v0.x; a0.y += v0.y; a0.z += v0.z; a0.w += v0.w;
        a1.x += v1.x; a1.y += v1.y; a1.z += v1.z; a1.w += v1.w;
    }
    if (n < n1) {
        float4 v = h4[(size_t)n * 128 + c];
        a0.x += v.x; a0.y += v.y; a0.z += v.z; a0.w += v.w;
    }
    a0.x += a1.x; a0.y += a1.y; a0.z += a1.z; a0.w += a1.w;
    uint2 uh, ul;
    split4(a0, uh, ul);
    reinterpret_cast<uint2*>(phi)[(size_t)g * 128 + c] = uh;
    reinterpret_cast<uint2*>(plo)[(size_t)g * 128 + c] = ul;
}

__global__ void pool_mean_k(const float* __restrict__ h, const int* __restrict__ goff,
                            float* __restrict__ out) {
    const int g = blockIdx.x, c = threadIdx.x;
    const float4* h4 = reinterpret_cast<const float4*>(h);
    float4 a0 = make_float4(0.f, 0.f, 0.f, 0.f);
    float4 a1 = make_float4(0.f, 0.f, 0.f, 0.f);
    const int n0 = __ldg(goff + g), n1 = __ldg(goff + g + 1);
    int n = n0;
    for (; n + 2 <= n1; n += 2) {
        float4 v0 = h4[(size_t)n * 128 + c];
        float4 v1 = h4[(size_t)(n + 1) * 128 + c];
        a0.x += v0.x; a0.y += v0.y; a0.z += v0.z; a0.w += v0.w;
        a1.x += v1.x; a1.y += v1.y; a1.z += v1.z; a1.w += v1.w;
    }
    if (n < n1) {
        float4 v = h4[(size_t)n * 128 + c];
        a0.x += v.x; a0.y += v.y; a0.z += v.z; a0.w += v.w;
    }
    float inv = 1.0f / fmaxf((float)(n1 - n0), 1.0f);
    a0.x = (a0.x + a1.x) * inv; a0.y = (a0.y + a1.y) * inv;
    a0.z = (a0.z + a1.z) * inv; a0.w = (a0.w + a1.w) * inv;
    reinterpret_cast<float4*>(out)[(size_t)g * 128 + c] = a0;
}

__global__ void vinit_k(float* __restrict__ vf, const float* __restrict__ vemb) {
    int idx = blockIdx.x * blockDim.x + threadIdx.x;
    if (idx >= kG * kH / 4) return;
    reinterpret_cast<float4*>(vf)[idx] =
        reinterpret_cast<const float4*>(vemb)[idx & (kH / 4 - 1)];
}

// ---------------- host launcher ----------------
static void run_gemm(const __nv_bfloat16* Ahi, const __nv_bfloat16* Alo,
                     const __nv_bfloat16* Bhi, const __nv_bfloat16* Blo,
                     const float* lb, const float* ga, const float* be,
                     float* C, __nv_bfloat16* Chi, __nv_bfloat16* Clo,
                     int M, int K, int Nc, bool relu, bool split) {
    dim3 grid(Nc / 128, (M + 127) / 128);
    if (split) {
        if (relu) gemm_bf16<1,1><<<grid, 256, DSMEM>>>(Ahi, Alo, Bhi, Blo, lb, ga, be, C, Chi, Clo, M, K, Nc);
        else      gemm_bf16<0,1><<<grid, 256, DSMEM>>>(Ahi, Alo, Bhi, Blo, lb, ga, be, C, Chi, Clo, M, K, Nc);
    } else {
        if (relu) gemm_bf16<1,0><<<grid, 256, DSMEM>>>(Ahi, Alo, Bhi, Blo, lb, ga, be, C, Chi, Clo, M, K, Nc);
        else      gemm_bf16<0,0><<<grid, 256, DSMEM>>>(Ahi, Alo, Bhi, Blo, lb, ga, be, C, Chi, Clo, M, K, Nc);
    }
}

static void run_split(const float* A, __nv_bfloat16* hi, __nv_bfloat16* lo, size_t n) {
    int n4 = (int)(n / 4);
    split_k<<<(n4 + 255) / 256, 256>>>(A, hi, lo, n4);
}

extern "C" void kernel_launch(void* const* d_in, const int* in_sizes, int n_in,
                              void* d_out, int out_size) {
    const float* x      = (const float*)d_in[0];
    const int*   ei     = (const int*)  d_in[1];
    const int*   batch  = (const int*)  d_in[2];
    const float* c1_W1  = (const float*)d_in[3];
    const float* c1_b1  = (const float*)d_in[4];
    const float* c1_g1  = (const float*)d_in[5];
    const float* c1_be1 = (const float*)d_in[6];
    const float* c1_W2  = (const float*)d_in[7];
    const float* c1_b2  = (const float*)d_in[8];
    const float* bn1_g  = (const float*)d_in[9];
    const float* bn1_b  = (const float*)d_in[10];
    const float* cs_W1  = (const float*)d_in[11];
    const float* cs_b1  = (const float*)d_in[12];
    const float* cs_g1  = (const float*)d_in[13];
    const float* cs_be1 = (const float*)d_in[14];
    const float* cs_W2  = (const float*)d_in[15];
    const float* cs_b2  = (const float*)d_in[16];
    const float* bns_g  = (const float*)d_in[17];
    const float* bns_b  = (const float*)d_in[18];
    const float* vemb   = (const float*)d_in[19];
    const float* v_W1   = (const float*)d_in[20];
    const float* v_b1   = (const float*)d_in[21];
    const float* v_g1   = (const float*)d_in[22];
    const float* v_be1  = (const float*)d_in[23];
    const float* v_W2   = (const float*)d_in[24];
    const float* v_b2   = (const float*)d_in[25];
    const float* v_g2   = (const float*)d_in[26];
    const float* v_be2  = (const float*)d_in[27];

    cudaFuncSetAttribute(gemm_bf16<0,0>, cudaFuncAttributeMaxDynamicSharedMemorySize, DSMEM);
    cudaFuncSetAttribute(gemm_bf16<0,1>, cudaFuncAttributeMaxDynamicSharedMemorySize, DSMEM);
    cudaFuncSetAttribute(gemm_bf16<1,0>, cudaFuncAttributeMaxDynamicSharedMemorySize, DSMEM);
    cudaFuncSetAttribute(gemm_bf16<1,1>, cudaFuncAttributeMaxDynamicSharedMemorySize, DSMEM);

    float *h, *vf;
    int *goff, *deg, *cur, *rowptr, *esrc;
    __nv_bfloat16 *wthi, *wtlo, *ahi, *alo, *bhi, *blo, *phi, *plo, *qhi, *qlo;
    cudaGetSymbolAddress((void**)&h,      g_h);
    cudaGetSymbolAddress((void**)&vf,     g_vf);
    cudaGetSymbolAddress((void**)&goff,   g_goff);
    cudaGetSymbolAddress((void**)&deg,    g_deg);
    cudaGetSymbolAddress((void**)&cur,    g_cur);
    cudaGetSymbolAddress((void**)&rowptr, g_rowptr);
    cudaGetSymbolAddress((void**)&esrc,   g_esrc);
    cudaGetSymbolAddress((void**)&wthi,   g_wthi);
    cudaGetSymbolAddress((void**)&wtlo,   g_wtlo);
    cudaGetSymbolAddress((void**)&ahi,    g_ahi);
    cudaGetSymbolAddress((void**)&alo,    g_alo);
    cudaGetSymbolAddress((void**)&bhi,    g_bhi);
    cudaGetSymbolAddress((void**)&blo,    g_blo);
    cudaGetSymbolAddress((void**)&phi,    g_phi);
    cudaGetSymbolAddress((void**)&plo,    g_plo);
    cudaGetSymbolAddress((void**)&qhi,    g_qhi);
    cudaGetSymbolAddress((void**)&qlo,    g_qlo);

    const int* srcI = ei;
    const int* dstI = ei + kE;

    // ---- early chain ordered so GEMM1 lands in ncu's -s 5 -c 1 window ----
    prep_k<<<128 + (kN + 255) / 256, 256>>>(c1_W1, wthi + OFF_c1W1, wtlo + OFF_c1W1, deg, cur);
    degcount_k<<<(kE + 255) / 256, 256>>>(dstI, deg);
    scan_k<<<1, 1024>>>(deg, rowptr);
    fill_k<<<(kE + 255) / 256, 256>>>(srcI, dstI, rowptr, cur, esrc);
    aggregate_k<kD,0><<<kN / 8, 256>>>(x, nullptr, nullptr, rowptr, esrc, ahi, alo);
    run_gemm(ahi, alo, wthi + OFF_c1W1, wtlo + OFF_c1W1, c1_b1, c1_g1, c1_be1,
             nullptr, bhi, blo, kN, kD, kH2, true, true);
    run_split(c1_W2, wthi + OFF_c1W2, wtlo + OFF_c1W2, (size_t)kH2 * kH);
    run_gemm(bhi, blo, wthi + OFF_c1W2, wtlo + OFF_c1W2, c1_b2, bn1_g, bn1_b,
             h, nullptr, nullptr, kN, kH2, kH, true, false);

    // remaining weight splits + graph metadata
    for (int i = 0; i < kL; i++) {
        run_split(cs_W1 + (size_t)i * kH * kH2,
                  wthi + OFF_csW1 + (size_t)i * kH * kH2,
                  wtlo + OFF_csW1 + (size_t)i * kH * kH2, (size_t)kH * kH2);
        run_split(cs_W2 + (size_t)i * kH2 * kH,
                  wthi + OFF_csW2 + (size_t)i * kH2 * kH,
                  wtlo + OFF_csW2 + (size_t)i * kH2 * kH, (size_t)kH2 * kH);
    }
    run_split(v_W1, wthi + OFF_vW1, wtlo + OFF_vW1, (size_t)kH * kH2);
    run_split(v_W2, wthi + OFF_vW2, wtlo + OFF_vW2, (size_t)kH2 * kH);
    vinit_k<<<(kG * kH / 4 + 255) / 256, 256>>>(vf, vemb);
    countgscan_k<<<1, 256>>>(batch, goff);

    // ---- L GIN layers with virtual node ----
    for (int i = 0; i < kL; i++) {
        aggregate_k<kH,1><<<kN / 2, 256>>>(h, vf, batch, rowptr, esrc, ahi, alo);
        run_gemm(ahi, alo, wthi + OFF_csW1 + (size_t)i * kH * kH2,
                 wtlo + OFF_csW1 + (size_t)i * kH * kH2,
                 cs_b1 + i * kH2, cs_g1 + i * kH2, cs_be1 + i * kH2,
                 nullptr, bhi, blo, kN, kH, kH2, true, true);
        run_gemm(bhi, blo, wthi + OFF_csW2 + (size_t)i * kH2 * kH,
                 wtlo + OFF_csW2 + (size_t)i * kH2 * kH,
                 cs_b2 + i * kH, bns_g + i * kH, bns_b + i * kH,
                 h, nullptr, nullptr, kN, kH2, kH, i < kL - 1, false);
        if (i < kL - 1) {
            pool_virt_k<<<kG, 128>>>(h, goff, vf, phi, plo);
            run_gemm(phi, plo, wthi + OFF_vW1, wtlo + OFF_vW1, v_b1, v_g1, v_be1,
                     nullptr, qhi, qlo, kG, kH, kH2, true, true);
            run_gemm(qhi, qlo, wthi + OFF_vW2, wtlo + OFF_vW2, v_b2, v_g2, v_be2,
                     vf, nullptr, nullptr, kG, kH2, kH, true, false);
        }
    }

    // ---- mean-pool readout into d_out ----
    pool_mean_k<<<kG, 128>>>(h, goff, (float*)d_out);
}

// round 16
// speedup vs baseline: 1.0284x; 1.0284x over previous
#include <cuda_runtime.h>
#include <cuda_bf16.h>
#include <mma.h>
#include <cstdint>

using namespace nvcuda;

// Problem constants
constexpr int kN  = 50000;
constexpr int kE  = 800000;
constexpr int kG  = 128;
constexpr int kD  = 128;
constexpr int kH  = 512;
constexpr int kH2 = 1024;
constexpr int kL  = 4;
#define BNS 0.9999950000374997f   // 1/sqrt(1+1e-5)

// ---------------- scratch (no cudaMalloc allowed) ----------------
__device__ float g_h   [(size_t)kN * kH];
__device__ float g_vf  [kG * kH];
__device__ int   g_goff[kG + 1];

// CSR structures
__device__ int g_deg   [kN];
__device__ int g_cur   [kN];
__device__ int g_rowptr[kN + 1];
__device__ int g_esrc  [kE];

// bf16 split buffers
__device__ __nv_bfloat16 g_ahi[(size_t)kN * kH];
__device__ __nv_bfloat16 g_alo[(size_t)kN * kH];
__device__ __nv_bfloat16 g_bhi[(size_t)kN * kH2];
__device__ __nv_bfloat16 g_blo[(size_t)kN * kH2];
__device__ __nv_bfloat16 g_phi[kG * kH];
__device__ __nv_bfloat16 g_plo[kG * kH];
__device__ __nv_bfloat16 g_qhi[kG * kH2];
__device__ __nv_bfloat16 g_qlo[kG * kH2];

// Split weights, layout [K, Nc] row-major, bf16 hi/lo
constexpr size_t OFF_c1W1 = 0;                            // [128,1024]
constexpr size_t OFF_c1W2 = OFF_c1W1 + 128 * 1024;        // [1024,512]
constexpr size_t OFF_csW1 = OFF_c1W2 + 1024 * 512;        // 4 x [512,1024]
constexpr size_t OFF_csW2 = OFF_csW1 + 4ull * 512 * 1024; // 4 x [1024,512]
constexpr size_t OFF_vW1  = OFF_csW2 + 4ull * 1024 * 512; // [512,1024]
constexpr size_t OFF_vW2  = OFF_vW1 + 512 * 1024;         // [1024,512]
constexpr size_t WT_TOTAL = OFF_vW2 + 1024 * 512;
__device__ __nv_bfloat16 g_wthi[WT_TOTAL];
__device__ __nv_bfloat16 g_wtlo[WT_TOTAL];

// ---------------- helpers ----------------
__device__ __forceinline__ uint32_t smem_u32(const void* p) {
    uint32_t a;
    asm("{ .reg .u64 t; cvta.to.shared.u64 t, %1; cvt.u32.u64 %0, t; }" : "=r"(a) : "l"(p));
    return a;
}
__device__ __forceinline__ void cp16(uint32_t saddr, const void* gaddr) {
    asm volatile("cp.async.cg.shared.global [%0], [%1], 16;" :: "r"(saddr), "l"(gaddr) : "memory");
}
#define CP_COMMIT() asm volatile("cp.async.commit_group;" ::: "memory")
#define CP_WAIT(n)  asm volatile("cp.async.wait_group %0;" :: "n"(n) : "memory")

// pack 4 floats -> bf16 hi/lo pairs
__device__ __forceinline__ void split4(float4 v, uint2& uh, uint2& ul) {
    unsigned short hx = __bfloat16_as_ushort(__float2bfloat16(v.x));
    unsigned short hy = __bfloat16_as_ushort(__float2bfloat16(v.y));
    unsigned short hz = __bfloat16_as_ushort(__float2bfloat16(v.z));
    unsigned short hw = __bfloat16_as_ushort(__float2bfloat16(v.w));
    float fx = __bfloat162float(__ushort_as_bfloat16(hx));
    float fy = __bfloat162float(__ushort_as_bfloat16(hy));
    float fz = __bfloat162float(__ushort_as_bfloat16(hz));
    float fw = __bfloat162float(__ushort_as_bfloat16(hw));
    unsigned short lx = __bfloat16_as_ushort(__float2bfloat16(v.x - fx));
    unsigned short ly = __bfloat16_as_ushort(__float2bfloat16(v.y - fy));
    unsigned short lz = __bfloat16_as_ushort(__float2bfloat16(v.z - fz));
    unsigned short lw = __bfloat16_as_ushort(__float2bfloat16(v.w - fw));
    uh.x = (uint32_t)hx | ((uint32_t)hy << 16);
    uh.y = (uint32_t)hz | ((uint32_t)hw << 16);
    ul.x = (uint32_t)lx | ((uint32_t)ly << 16);
    ul.y = (uint32_t)lz | ((uint32_t)lw << 16);
}

// ---------------- GEMM smem layout (tile 128x128, BK=32, 2 stages) ----------------
constexpr int A_LD   = 40;                  // 32 + 8 pad
constexpr int B_LD   = 136;                 // 128 + 8 pad
constexpr int A_MATB = 128 * A_LD * 2;      // 10240
constexpr int B_MATB = 32 * B_LD * 2;       // 8704
constexpr int ST_AH  = 0;
constexpr int ST_AL  = A_MATB;
constexpr int ST_BH  = 2 * A_MATB;
constexpr int ST_BL  = 2 * A_MATB + B_MATB;
constexpr int STAGE  = 2 * A_MATB + 2 * B_MATB; // 37888
constexpr int NSTG   = 2;
constexpr int OFF_SC = NSTG * STAGE;        // 75776
constexpr int OFF_SH = OFF_SC + 512;
constexpr int DSMEM  = OFF_SH + 512;        // 76800  (x2 CTAs = 150KB <= 228KB)

// ---------------- bf16-split GEMM: out = act((A@W + lb)*(ga*BNS) + be) ----------------
// CTA 128x128, 4 warps (2x2), warp tile 64x64, wmma 16x16x16, 3-term split,
// 2-stage cp.async, 2 CTAs/SM. 128 threads/CTA -> 256 regs/thread budget:
// acc 4x4 (128 regs) fits without spills; halves smem fragment redundancy vs 8-warp 32x64.
template<int RELU, int SPLIT>
__global__ void __launch_bounds__(128, 2) gemm_bf16(
    const __nv_bfloat16* __restrict__ Ahi, const __nv_bfloat16* __restrict__ Alo,
    const __nv_bfloat16* __restrict__ Bhi, const __nv_bfloat16* __restrict__ Blo,
    const float* __restrict__ lb, const float* __restrict__ ga,
    const float* __restrict__ be, float* __restrict__ C,
    __nv_bfloat16* __restrict__ Chi, __nv_bfloat16* __restrict__ Clo,
    int M, int K, int Nc)
{
    extern __shared__ char sm[];
    const uint32_t sbase = smem_u32(sm);

    const int tid  = threadIdx.x;
    const int warp = tid >> 5, lane = tid & 31;
    const int wm   = warp >> 1, wn = warp & 1;   // 2x2 layout, warp tile 64x64
    const int bm0  = blockIdx.y * 128, bn0 = blockIdx.x * 128;

    {   // fused BN params for this 128-column tile (128 threads cover it)
        float s = ga[bn0 + tid] * BNS;
        ((float*)(sm + OFF_SC))[tid] = s;
        ((float*)(sm + OFF_SH))[tid] = fmaf(lb[bn0 + tid], s, be[bn0 + tid]);
    }

    wmma::fragment<wmma::accumulator, 16, 16, 16, float> acc[4][4];
#pragma unroll
    for (int i = 0; i < 4; i++)
#pragma unroll
        for (int j = 0; j < 4; j++) wmma::fill_fragment(acc[i][j], 0.0f);

    const int nK = K >> 5;

    auto issue = [&](int c) {
        const int buf = c & 1;
        const int k0  = c << 5;
        const uint32_t sb = sbase + buf * STAGE;
        // A: 512 16B chunks per matrix (128 rows x 32 cols), 4 per thread
#pragma unroll
        for (int t = 0; t < 4; t++) {
            int chunk = tid + (t << 7);
            int row   = chunk >> 2;
            int col8  = (chunk & 3) << 3;
            int gr    = bm0 + row;
            if (gr < M) {
                uint32_t off = (uint32_t)(row * A_LD + col8) * 2;
                size_t g = (size_t)gr * K + k0 + col8;
                cp16(sb + ST_AH + off, Ahi + g);
                cp16(sb + ST_AL + off, Alo + g);
            }
        }
        // B: 512 chunks per matrix (32 rows x 128 cols), 4 per thread
#pragma unroll
        for (int t = 0; t < 4; t++) {
            int chunk = tid + (t << 7);
            int row   = chunk >> 4;
            int col8  = (chunk & 15) << 3;
            uint32_t off = (uint32_t)(row * B_LD + col8) * 2;
            size_t g = (size_t)(k0 + row) * Nc + bn0 + col8;
            cp16(sb + ST_BH + off, Bhi + g);
            cp16(sb + ST_BL + off, Blo + g);
        }
        CP_COMMIT();
    };

    issue(0);
    for (int c = 0; c < nK; c++) {
        if (c + 1 < nK) { issue(c + 1); CP_WAIT(1); }
        else            { CP_WAIT(0); }
        __syncthreads();

        const char* st = sm + (c & 1) * STAGE;
        const __nv_bfloat16* sAh = (const __nv_bfloat16*)(st + ST_AH);
        const __nv_bfloat16* sAl = (const __nv_bfloat16*)(st + ST_AL);
        const __nv_bfloat16* sBh = (const __nv_bfloat16*)(st + ST_BH);
        const __nv_bfloat16* sBl = (const __nv_bfloat16*)(st + ST_BL);
#pragma unroll
        for (int ks = 0; ks < 2; ks++) {
            const int kk = ks << 4;
            wmma::fragment<wmma::matrix_a, 16, 16, 16, __nv_bfloat16, wmma::row_major> ah[4], al[4];
#pragma unroll
            for (int i = 0; i < 4; i++) {
                wmma::load_matrix_sync(ah[i], sAh + (wm * 64 + i * 16) * A_LD + kk, A_LD);
                wmma::load_matrix_sync(al[i], sAl + (wm * 64 + i * 16) * A_LD + kk, A_LD);
            }
#pragma unroll
            for (int j = 0; j < 4; j++) {
                wmma::fragment<wmma::matrix_b, 16, 16, 16, __nv_bfloat16, wmma::row_major> bh, bl;
                wmma::load_matrix_sync(bh, sBh + kk * B_LD + wn * 64 + j * 16, B_LD);
                wmma::load_matrix_sync(bl, sBl + kk * B_LD + wn * 64 + j * 16, B_LD);
#pragma unroll
                for (int i = 0; i < 4; i++) {
                    wmma::mma_sync(acc[i][j], ah[i], bh, acc[i][j]);
                    wmma::mma_sync(acc[i][j], ah[i], bl, acc[i][j]);
                    wmma::mma_sync(acc[i][j], al[i], bh, acc[i][j]);
                }
            }
        }
        __syncthreads();
    }

    // epilogue: stage 16x16 tiles via smem, fused BN/bias/ReLU (+optional split)
    float* stage = (float*)(sm + warp * 1280);   // 4 warps * 1280B, clears pipeline smem (done)
    const float* sc = (const float*)(sm + OFF_SC);
    const float* sh = (const float*)(sm + OFF_SH);
#pragma unroll
    for (int i = 0; i < 4; i++)
#pragma unroll
        for (int j = 0; j < 4; j++) {
            __syncwarp();
            wmma::store_matrix_sync(stage, acc[i][j], 20, wmma::mem_row_major);
            __syncwarp();
#pragma unroll
            for (int t = lane; t < 256; t += 32) {
                int r   = t >> 4, cc = t & 15;
                int gr  = bm0 + wm * 64 + i * 16 + r;
                int gcl = wn * 64 + j * 16 + cc;
                if (gr < M) {
                    float o = fmaf(stage[r * 20 + cc], sc[gcl], sh[gcl]);
                    if (RELU) o = fmaxf(o, 0.0f);
                    size_t idx = (size_t)gr * Nc + bn0 + gcl;
                    if (SPLIT) {
                        __nv_bfloat16 hi = __float2bfloat16(o);
                        Chi[idx] = hi;
                        Clo[idx] = __float2bfloat16(o - __bfloat162float(hi));
                    } else {
                        C[idx] = o;
                    }
                }
            }
        }
}

// ---------------- prep: zero deg/cur + split c1_W1 to bf16 hi/lo ----------------
__global__ void prep_k(const float* __restrict__ W,
                       __nv_bfloat16* __restrict__ hi, __nv_bfloat16* __restrict__ lo,
                       int* __restrict__ deg, int* __restrict__ cur) {
    int b = blockIdx.x;
    if (b < 128) {
        int i = b * 256 + threadIdx.x;
        uint2 uh, ul;
        split4(reinterpret_cast<const float4*>(W)[i], uh, ul);
        reinterpret_cast<uint2*>(hi)[i] = uh;
        reinterpret_cast<uint2*>(lo)[i] = ul;
    } else {
        int i = (b - 128) * 256 + threadIdx.x;
        if (i < kN) { deg[i] = 0; cur[i] = 0; }
    }
}

// ---------------- fp32 -> bf16 hi/lo split (weights) ----------------
__global__ void split_k(const float* __restrict__ A, __nv_bfloat16* __restrict__ hi,
                        __nv_bfloat16* __restrict__ lo, int n4) {
    int i = blockIdx.x * blockDim.x + threadIdx.x;
    if (i >= n4) return;
    uint2 uh, ul;
    split4(reinterpret_cast<const float4*>(A)[i], uh, ul);
    reinterpret_cast<uint2*>(hi)[i] = uh;
    reinterpret_cast<uint2*>(lo)[i] = ul;
}

// ---------------- CSR build ----------------
__global__ void degcount_k(const int* __restrict__ dst, int* __restrict__ deg) {
    int e = blockIdx.x * blockDim.x + threadIdx.x;
    if (e < kE) atomicAdd(&deg[__ldg(dst + e)], 1);
}

__global__ void scan_k(const int* __restrict__ deg, int* __restrict__ rowptr) {
    __shared__ int part[1024];
    __shared__ int total;
    const int t  = threadIdx.x;
    const int CH = (kN + 1023) / 1024;
    int start = t * CH;
    int end   = start + CH; if (end > kN) end = kN;
    int s = 0;
    for (int i = start; i < end; i++) s += deg[i];
    part[t] = s;
    __syncthreads();
    if (t == 0) {
        int run = 0;
        for (int j = 0; j < 1024; j++) { int v = part[j]; part[j] = run; run += v; }
        total = run;
    }
    __syncthreads();
    int run = part[t];
    for (int i = start; i < end; i++) { rowptr[i] = run; run += deg[i]; }
    if (t == 0) rowptr[kN] = total;
}

__global__ void fill_k(const int* __restrict__ src, const int* __restrict__ dst,
                       const int* __restrict__ rowptr, int* __restrict__ cur,
                       int* __restrict__ esrc) {
    int e = blockIdx.x * blockDim.x + threadIdx.x;
    if (e >= kE) return;
    int d = __ldg(dst + e);
    int pos = rowptr[d] + atomicAdd(&cur[d], 1);
    esrc[pos] = __ldg(src + e);
}

// ---------------- graph offsets: histogram + scan of sorted batch ----------------
__global__ void countgscan_k(const int* __restrict__ batch, int* __restrict__ goff) {
    __shared__ int scnt[kG];
    const int t = threadIdx.x;
    for (int g = t; g < kG; g += blockDim.x) scnt[g] = 0;
    __syncthreads();
    for (int n = t; n < kN; n += blockDim.x) atomicAdd(&scnt[__ldg(batch + n)], 1);
    __syncthreads();
    if (t == 0) {
        int run = 0;
        for (int g = 0; g < kG; g++) { goff[g] = run; run += scnt[g]; }
        goff[kG] = run;
    }
}

// ---------------- CSR gather aggregation (+virtual add) + fused bf16 hi/lo split ----------------
template<int F, int VIRT>
__global__ void __launch_bounds__(256) aggregate_k(
    const float* __restrict__ feat, const float* __restrict__ vf,
    const int* __restrict__ batch,
    const int* __restrict__ rowptr, const int* __restrict__ esrc,
    __nv_bfloat16* __restrict__ hi, __nv_bfloat16* __restrict__ lo)
{
    constexpr int C4  = F / 4;
    constexpr int NPB = 256 / C4;
    const int n = blockIdx.x * NPB + (threadIdx.x / C4);
    const int c = threadIdx.x & (C4 - 1);
    const float4* f4  = reinterpret_cast<const float4*>(feat);
    const float4* vf4 = reinterpret_cast<const float4*>(vf);
    float4 acc = f4[(size_t)n * C4 + c];
    if (VIRT) {
        float4 v = vf4[(size_t)__ldg(batch + n) * C4 + c];
        acc.x += v.x; acc.y += v.y; acc.z += v.z; acc.w += v.w;
    }
    const int p0 = __ldg(rowptr + n), p1 = __ldg(rowptr + n + 1);
    int p = p0;
    for (; p + 4 <= p1; p += 4) {
        int s0 = __ldg(esrc + p),     s1 = __ldg(esrc + p + 1);
        int s2 = __ldg(esrc + p + 2), s3 = __ldg(esrc + p + 3);
        float4 v0 = f4[(size_t)s0 * C4 + c];
        float4 v1 = f4[(size_t)s1 * C4 + c];
        float4 v2 = f4[(size_t)s2 * C4 + c];
        float4 v3 = f4[(size_t)s3 * C4 + c];
        if (VIRT) {
            float4 w0 = vf4[(size_t)__ldg(batch + s0) * C4 + c];
            float4 w1 = vf4[(size_t)__ldg(batch + s1) * C4 + c];
            float4 w2 = vf4[(size_t)__ldg(batch + s2) * C4 + c];
            float4 w3 = vf4[(size_t)__ldg(batch + s3) * C4 + c];
            v0.x += w0.x; v0.y += w0.y; v0.z += w0.z; v0.w += w0.w;
            v1.x += w1.x; v1.y += w1.y; v1.z += w1.z; v1.w += w1.w;
            v2.x += w2.x; v2.y += w2.y; v2.z += w2.z; v2.w += w2.w;
            v3.x += w3.x; v3.y += w3.y; v3.z += w3.z; v3.w += w3.w;
        }
        acc.x += (v0.x + v1.x) + (v2.x + v3.x);
        acc.y += (v0.y + v1.y) + (v2.y + v3.y);
        acc.z += (v0.z + v1.z) + (v2.z + v3.z);
        acc.w += (v0.w + v1.w) + (v2.w + v3.w);
    }
    for (; p < p1; p++) {
        int s = __ldg(esrc + p);
        float4 v = f4[(size_t)s * C4 + c];
        if (VIRT) {
            float4 w = vf4[(size_t)__ldg(batch + s) * C4 + c];
            v.x += w.x; v.y += w.y; v.z += w.z; v.w += w.w;
        }
        acc.x += v.x; acc.y += v.y; acc.z += v.z; acc.w += v.w;
    }
    uint2 uh, ul;
    split4(acc, uh, ul);
    reinterpret_cast<uint2*>(hi)[(size_t)n * C4 + c] = uh;
    reinterpret_cast<uint2*>(lo)[(size_t)n * C4 + c] = ul;
}

// ---------------- segmented pools over sorted batch ----------------
__global__ void pool_virt_k(const float* __restrict__ h, const int* __restrict__ goff,
                            const float* __restrict__ vf,
                            __nv_bfloat16* __restrict__ phi, __nv_bfloat16* __restrict__ plo) {
    const int g = blockIdx.x, c = threadIdx.x;
    const float4* h4 = reinterpret_cast<const float4*>(h);
    float4 a0 = reinterpret_cast<const float4*>(vf)[(size_t)g * 128 + c];
    float4 a1 = make_float4(0.f, 0.f, 0.f, 0.f);
    const int n0 = __ldg(goff + g), n1 = __ldg(goff + g + 1);
    int n = n0;
    for (; n + 2 <= n1; n += 2) {
        float4 v0 = h4[(size_t)n * 128 + c];
        float4 v1 = h4[(size_t)(n + 1) * 128 + c];
        a0.x += v0.x; a0.y += v0.y; a0.z += v0.z; a0.w += v0.w;
        a1.x += v1.x; a1.y += v1.y; a1.z += v1.z; a1.w += v1.w;
    }
    if (n < n1) {
        float4 v = h4[(size_t)n * 128 + c];
        a0.x += v.x; a0.y += v.y; a0.z += v.z; a0.w += v.w;
    }
    a0.x += a1.x; a0.y += a1.y; a0.z += a1.z; a0.w += a1.w;
    uint2 uh, ul;
    split4(a0, uh, ul);
    reinterpret_cast<uint2*>(phi)[(size_t)g * 128 + c] = uh;
    reinterpret_cast<uint2*>(plo)[(size_t)g * 128 + c] = ul;
}

__global__ void pool_mean_k(const float* __restrict__ h, const int* __restrict__ goff,
                            float* __restrict__ out) {
    const int g = blockIdx.x, c = threadIdx.x;
    const float4* h4 = reinterpret_cast<const float4*>(h);
    float4 a0 = make_float4(0.f, 0.f, 0.f, 0.f);
    float4 a1 = make_float4(0.f, 0.f, 0.f, 0.f);
    const int n0 = __ldg(goff + g), n1 = __ldg(goff + g + 1);
    int n = n0;
    for (; n + 2 <= n1; n += 2) {
        float4 v0 = h4[(size_t)n * 128 + c];
        float4 v1 = h4[(size_t)(n + 1) * 128 + c];
        a0.x += v0.x; a0.y += v0.y; a0.z += v0.z; a0.w += v0.w;
        a1.x += v1.x; a1.y += v1.y; a1.z += v1.z; a1.w += v1.w;
    }
    if (n < n1) {
        float4 v = h4[(size_t)n * 128 + c];
        a0.x += v.x; a0.y += v.y; a0.z += v.z; a0.w += v.w;
    }
    float inv = 1.0f / fmaxf((float)(n1 - n0), 1.0f);
    a0.x = (a0.x + a1.x) * inv; a0.y = (a0.y + a1.y) * inv;
    a0.z = (a0.z + a1.z) * inv; a0.w = (a0.w + a1.w) * inv;
    reinterpret_cast<float4*>(out)[(size_t)g * 128 + c] = a0;
}

__global__ void vinit_k(float* __restrict__ vf, const float* __restrict__ vemb) {
    int idx = blockIdx.x * blockDim.x + threadIdx.x;
    if (idx >= kG * kH / 4) return;
    reinterpret_cast<float4*>(vf)[idx] =
        reinterpret_cast<const float4*>(vemb)[idx & (kH / 4 - 1)];
}

// ---------------- host launcher ----------------
static void run_gemm(const __nv_bfloat16* Ahi, const __nv_bfloat16* Alo,
                     const __nv_bfloat16* Bhi, const __nv_bfloat16* Blo,
                     const float* lb, const float* ga, const float* be,
                     float* C, __nv_bfloat16* Chi, __nv_bfloat16* Clo,
                     int M, int K, int Nc, bool relu, bool split) {
    dim3 grid(Nc / 128, (M + 127) / 128);
    if (split) {
        if (relu) gemm_bf16<1,1><<<grid, 128, DSMEM>>>(Ahi, Alo, Bhi, Blo, lb, ga, be, C, Chi, Clo, M, K, Nc);
        else      gemm_bf16<0,1><<<grid, 128, DSMEM>>>(Ahi, Alo, Bhi, Blo, lb, ga, be, C, Chi, Clo, M, K, Nc);
    } else {
        if (relu) gemm_bf16<1,0><<<grid, 128, DSMEM>>>(Ahi, Alo, Bhi, Blo, lb, ga, be, C, Chi, Clo, M, K, Nc);
        else      gemm_bf16<0,0><<<grid, 128, DSMEM>>>(Ahi, Alo, Bhi, Blo, lb, ga, be, C, Chi, Clo, M, K, Nc);
    }
}

static void run_split(const float* A, __nv_bfloat16* hi, __nv_bfloat16* lo, size_t n) {
    int n4 = (int)(n / 4);
    split_k<<<(n4 + 255) / 256, 256>>>(A, hi, lo, n4);
}

extern "C" void kernel_launch(void* const* d_in, const int* in_sizes, int n_in,
                              void* d_out, int out_size) {
    const float* x      = (const float*)d_in[0];
    const int*   ei     = (const int*)  d_in[1];
    const int*   batch  = (const int*)  d_in[2];
    const float* c1_W1  = (const float*)d_in[3];
    const float* c1_b1  = (const float*)d_in[4];
    const float* c1_g1  = (const float*)d_in[5];
    const float* c1_be1 = (const float*)d_in[6];
    const float* c1_W2  = (const float*)d_in[7];
    const float* c1_b2  = (const float*)d_in[8];
    const float* bn1_g  = (const float*)d_in[9];
    const float* bn1_b  = (const float*)d_in[10];
    const float* cs_W1  = (const float*)d_in[11];
    const float* cs_b1  = (const float*)d_in[12];
    const float* cs_g1  = (const float*)d_in[13];
    const float* cs_be1 = (const float*)d_in[14];
    const float* cs_W2  = (const float*)d_in[15];
    const float* cs_b2  = (const float*)d_in[16];
    const float* bns_g  = (const float*)d_in[17];
    const float* bns_b  = (const float*)d_in[18];
    const float* vemb   = (const float*)d_in[19];
    const float* v_W1   = (const float*)d_in[20];
    const float* v_b1   = (const float*)d_in[21];
    const float* v_g1   = (const float*)d_in[22];
    const float* v_be1  = (const float*)d_in[23];
    const float* v_W2   = (const float*)d_in[24];
    const float* v_b2   = (const float*)d_in[25];
    const float* v_g2   = (const float*)d_in[26];
    const float* v_be2  = (const float*)d_in[27];

    cudaFuncSetAttribute(gemm_bf16<0,0>, cudaFuncAttributeMaxDynamicSharedMemorySize, DSMEM);
    cudaFuncSetAttribute(gemm_bf16<0,1>, cudaFuncAttributeMaxDynamicSharedMemorySize, DSMEM);
    cudaFuncSetAttribute(gemm_bf16<1,0>, cudaFuncAttributeMaxDynamicSharedMemorySize, DSMEM);
    cudaFuncSetAttribute(gemm_bf16<1,1>, cudaFuncAttributeMaxDynamicSharedMemorySize, DSMEM);

    float *h, *vf;
    int *goff, *deg, *cur, *rowptr, *esrc;
    __nv_bfloat16 *wthi, *wtlo, *ahi, *alo, *bhi, *blo, *phi, *plo, *qhi, *qlo;
    cudaGetSymbolAddress((void**)&h,      g_h);
    cudaGetSymbolAddress((void**)&vf,     g_vf);
    cudaGetSymbolAddress((void**)&goff,   g_goff);
    cudaGetSymbolAddress((void**)&deg,    g_deg);
    cudaGetSymbolAddress((void**)&cur,    g_cur);
    cudaGetSymbolAddress((void**)&rowptr, g_rowptr);
    cudaGetSymbolAddress((void**)&esrc,   g_esrc);
    cudaGetSymbolAddress((void**)&wthi,   g_wthi);
    cudaGetSymbolAddress((void**)&wtlo,   g_wtlo);
    cudaGetSymbolAddress((void**)&ahi,    g_ahi);
    cudaGetSymbolAddress((void**)&alo,    g_alo);
    cudaGetSymbolAddress((void**)&bhi,    g_bhi);
    cudaGetSymbolAddress((void**)&blo,    g_blo);
    cudaGetSymbolAddress((void**)&phi,    g_phi);
    cudaGetSymbolAddress((void**)&plo,    g_plo);
    cudaGetSymbolAddress((void**)&qhi,    g_qhi);
    cudaGetSymbolAddress((void**)&qlo,    g_qlo);

    const int* srcI = ei;
    const int* dstI = ei + kE;

    // ---- early chain ----
    prep_k<<<128 + (kN + 255) / 256, 256>>>(c1_W1, wthi + OFF_c1W1, wtlo + OFF_c1W1, deg, cur);
    degcount_k<<<(kE + 255) / 256, 256>>>(dstI, deg);
    scan_k<<<1, 1024>>>(deg, rowptr);
    fill_k<<<(kE + 255) / 256, 256>>>(srcI, dstI, rowptr, cur, esrc);
    aggregate_k<kD,0><<<kN / 8, 256>>>(x, nullptr, nullptr, rowptr, esrc, ahi, alo);
    run_gemm(ahi, alo, wthi + OFF_c1W1, wtlo + OFF_c1W1, c1_b1, c1_g1, c1_be1,
             nullptr, bhi, blo, kN, kD, kH2, true, true);
    run_split(c1_W2, wthi + OFF_c1W2, wtlo + OFF_c1W2, (size_t)kH2 * kH);
    run_gemm(bhi, blo, wthi + OFF_c1W2, wtlo + OFF_c1W2, c1_b2, bn1_g, bn1_b,
             h, nullptr, nullptr, kN, kH2, kH, true, false);

    // remaining weight splits + graph metadata
    for (int i = 0; i < kL; i++) {
        run_split(cs_W1 + (size_t)i * kH * kH2,
                  wthi + OFF_csW1 + (size_t)i * kH * kH2,
                  wtlo + OFF_csW1 + (size_t)i * kH * kH2, (size_t)kH * kH2);
        run_split(cs_W2 + (size_t)i * kH2 * kH,
                  wthi + OFF_csW2 + (size_t)i * kH2 * kH,
                  wtlo + OFF_csW2 + (size_t)i * kH2 * kH, (size_t)kH2 * kH);
    }
    run_split(v_W1, wthi + OFF_vW1, wtlo + OFF_vW1, (size_t)kH * kH2);
    run_split(v_W2, wthi + OFF_vW2, wtlo + OFF_vW2, (size_t)kH2 * kH);
    vinit_k<<<(kG * kH / 4 + 255) / 256, 256>>>(vf, vemb);
    countgscan_k<<<1, 256>>>(batch, goff);

    // ---- L GIN layers with virtual node ----
    for (int i = 0; i < kL; i++) {
        aggregate_k<kH,1><<<kN / 2, 256>>>(h, vf, batch, rowptr, esrc, ahi, alo);
        run_gemm(ahi, alo, wthi + OFF_csW1 + (size_t)i * kH * kH2,
                 wtlo + OFF_csW1 + (size_t)i * kH * kH2,
                 cs_b1 + i * kH2, cs_g1 + i * kH2, cs_be1 + i * kH2,
                 nullptr, bhi, blo, kN, kH, kH2, true, true);
        run_gemm(bhi, blo, wthi + OFF_csW2 + (size_t)i * kH2 * kH,
                 wtlo + OFF_csW2 + (size_t)i * kH2 * kH,
                 cs_b2 + i * kH, bns_g + i * kH, bns_b + i * kH,
                 h, nullptr, nullptr, kN, kH2, kH, i < kL - 1, false);
        if (i < kL - 1) {
            pool_virt_k<<<kG, 128>>>(h, goff, vf, phi, plo);
            run_gemm(phi, plo, wthi + OFF_vW1, wtlo + OFF_vW1, v_b1, v_g1, v_be1,
                     nullptr, qhi, qlo, kG, kH, kH2, true, true);
            run_gemm(qhi, qlo, wthi + OFF_vW2, wtlo + OFF_vW2, v_b2, v_g2, v_be2,
                     vf, nullptr, nullptr, kG, kH2, kH, true, false);
        }
    }

    // ---- mean-pool readout into d_out ----
    pool_mean_k<<<kG, 128>>>(h, goff, (float*)d_out);
}